// round 8
// baseline (speedup 1.0000x reference)
#include <cuda_runtime.h>
#include <cuda_fp16.h>
#include <cstdint>
#include <cstddef>

// ---------------------------------------------------------------------------
// Geometry
// ---------------------------------------------------------------------------
static constexpr int KF = 4096;
static constexpr int NF = 14336;
static constexpr int MROWS = 256;
static constexpr int NTILE = 64;               // per-CTA n extent
static constexpr int KQ = 4;                   // k quarters
static constexpr int GRID = (NF / NTILE) * KQ; // 896
static constexpr int KC = 64;                  // k per stage
static constexpr int NITER_L = KF / KC / KQ;   // 16 chunks per CTA

// fp16 image of x, pre-swizzled as A smem tile images:
// 64 tiles (one per 64-k chunk), each 256 rows x 128B = 32KB.
__device__ __align__(128) unsigned char g_xs[64 * 32768];

// SMEM: A 2 x 32768 | B 2 x 8192  (per CTA)
static constexpr uint32_t SM_A = 0;
static constexpr uint32_t SM_B = 65536;
static constexpr uint32_t SM_TOTAL = 81920;

// ---------------------------------------------------------------------------
// Helpers
// ---------------------------------------------------------------------------
__device__ __forceinline__ __half2 u2h(uint32_t u) { return *reinterpret_cast<__half2*>(&u); }
__device__ __forceinline__ uint32_t h2u(__half2 h) { return *reinterpret_cast<uint32_t*>(&h); }

__device__ __forceinline__ void ldsm_x4(uint32_t (&r)[4], uint32_t addr) {
    asm volatile("ldmatrix.sync.aligned.m8n8.x4.shared.b16 {%0,%1,%2,%3}, [%4];"
                 : "=r"(r[0]), "=r"(r[1]), "=r"(r[2]), "=r"(r[3]) : "r"(addr));
}
__device__ __forceinline__ void ldsm_x4_t(uint32_t& r0, uint32_t& r1, uint32_t& r2, uint32_t& r3,
                                          uint32_t addr) {
    asm volatile("ldmatrix.sync.aligned.m8n8.x4.trans.shared.b16 {%0,%1,%2,%3}, [%4];"
                 : "=r"(r0), "=r"(r1), "=r"(r2), "=r"(r3) : "r"(addr));
}
__device__ __forceinline__ void mma16816(float (&d)[4], const uint32_t (&a)[4],
                                         uint32_t b0, uint32_t b1) {
    asm volatile("mma.sync.aligned.m16n8k16.row.col.f32.f16.f16.f32 "
                 "{%0,%1,%2,%3}, {%4,%5,%6,%7}, {%8,%9}, {%0,%1,%2,%3};"
                 : "+f"(d[0]), "+f"(d[1]), "+f"(d[2]), "+f"(d[3])
                 : "r"(a[0]), "r"(a[1]), "r"(a[2]), "r"(a[3]), "r"(b0), "r"(b1));
}

// ---------------------------------------------------------------------------
// Kernel 1: x fp32 -> fp16 pre-swizzled A tile images.
// byte(m, kl) = m*128 + (((kl>>3)^(m&7))<<4) + (kl&7)*2
// ---------------------------------------------------------------------------
__global__ __launch_bounds__(256) void prep_x_kernel(const float* __restrict__ x) {
    int idx = blockIdx.x * 256 + threadIdx.x;
    int m = idx >> 11;
    int k = (idx & 2047) * 2;
    float2 v = *reinterpret_cast<const float2*>(x + (size_t)m * KF + k);
    __half2 h = __floats2half2_rn(v.x, v.y);
    int c = k >> 6, kl = k & 63;
    uint32_t off = (uint32_t)m * 128u + ((((uint32_t)(kl >> 3)) ^ (uint32_t)(m & 7)) << 4)
                 + (uint32_t)(kl & 7) * 2u;
    *reinterpret_cast<uint32_t*>(g_xs + (size_t)c * 32768 + off) = h2u(h);
}

// ---------------------------------------------------------------------------
// Kernel 1b: out[m][n] = bias[n]  (float4 per thread)
// ---------------------------------------------------------------------------
__global__ __launch_bounds__(256) void init_out_kernel(const float* __restrict__ bias,
                                                       float* __restrict__ out) {
    int idx = blockIdx.x * 256 + threadIdx.x;      // 917504 float4s
    int m  = idx / (NF / 4);
    int n4 = idx % (NF / 4);
    float4 b4 = *reinterpret_cast<const float4*>(bias + n4 * 4);
    *reinterpret_cast<float4*>(out + (size_t)m * NF + n4 * 4) = b4;
}

// ---------------------------------------------------------------------------
// Kernel 2: GEMM. 896 CTAs x 128 threads (4 warps), 2 CTAs/SM.
// CTA: M=256, N=64, K=1024 (quarter). Warps 4(m) x 1(n); warp tile 64x64.
// Partial sums merged with red.global.add.f32 into bias-initialized out.
// ---------------------------------------------------------------------------
__global__ __launch_bounds__(128, 2)
void gemm_kernel(const int* __restrict__ qk, const float* __restrict__ qs,
                 const float* __restrict__ qzb, float* __restrict__ out) {
    extern __shared__ unsigned char smem[];
    const uint32_t sb = (uint32_t)__cvta_generic_to_shared(smem);
    const int t = threadIdx.x, lane = t & 31, w = t >> 5;
    const int n0 = (blockIdx.x >> 2) * NTILE;
    const int c0 = (blockIdx.x & 3) * NITER_L;     // first k-chunk of this quarter

    // ---- dequant mapping: nq = n quad (0..15), kw = k row base (0..7) ----
    const int nq = t & 15;
    const int kw = t >> 4;
    const uint32_t sts_base = (uint32_t)kw * 128u
                            + ((uint32_t)((nq >> 1) ^ kw) << 4) + (uint32_t)(nq & 1) * 8u;
    const int*   qbase = qk  + n0 + nq * 4;
    const float* sbase = qs  + n0 + nq * 4;
    const float* zbase = qzb + n0 + nq * 4;

    // ---- ldmatrix addressing ----
    const int l15 = lane & 15;
    const uint32_t sx = (uint32_t)(lane & 7);
    const uint32_t lq = (uint32_t)(lane >> 4);
    uint32_t a_row[4];
#pragma unroll
    for (int mb = 0; mb < 4; mb++)
        a_row[mb] = (uint32_t)(w * 64 + mb * 16 + l15) * 128u;
    const uint32_t b_row = (uint32_t)l15 * 128u;

    float d[4][8][4];
#pragma unroll
    for (int mb = 0; mb < 4; mb++)
#pragma unroll
        for (int nb = 0; nb < 8; nb++)
#pragma unroll
            for (int i = 0; i < 4; i++) d[mb][nb][i] = 0.0f;

    int4 bq4[4];
    uint32_t s01, s23, z01, z23;

    // ---- A prefetch: 32KB identity cp.async of pre-swizzled image ----
    auto prefetch_a = [&](int c, int st) {
        const unsigned char* asrc = g_xs + (size_t)c * 32768 + (size_t)t * 16;
        uint32_t adst = sb + SM_A + (uint32_t)st * 32768u + (uint32_t)t * 16u;
#pragma unroll
        for (int i = 0; i < 16; i++) {
            asm volatile("cp.async.cg.shared.global [%0], [%1], 16;"
                         :: "r"(adst + (uint32_t)i * 2048u), "l"(asrc + (size_t)i * 2048)
                         : "memory");
        }
        asm volatile("cp.async.commit_group;" ::: "memory");
    };

    auto load_scales = [&](int c) {
        int g = c >> 1;
        float4 s4 = *reinterpret_cast<const float4*>(sbase + (size_t)g * NF);
        float4 z4 = *reinterpret_cast<const float4*>(zbase + (size_t)g * NF);
        s01 = h2u(__floats2half2_rn(s4.x, s4.y)); s23 = h2u(__floats2half2_rn(s4.z, s4.w));
        z01 = h2u(__floats2half2_rn(z4.x, z4.y)); z23 = h2u(__floats2half2_rn(z4.z, z4.w));
    };

    auto ldg_b = [&](int c, int h) {           // rows k = kw + 8*(4h + j)
        const int* qp = qbase + (size_t)c * KC * NF + (size_t)(32 * h) * NF;
#pragma unroll
        for (int j = 0; j < 4; j++)
            bq4[j] = *reinterpret_cast<const int4*>(qp + (size_t)(kw + 8 * j) * NF);
    };

    auto store_b = [&](int st, int h) {
        const __half2 h1024 = u2h(0x64006400u);
        uint32_t base = sb + SM_B + (uint32_t)st * 8192u + sts_base + (uint32_t)h * 4096u;
#pragma unroll
        for (int j = 0; j < 4; j++) {
            uint32_t u01 = ((uint32_t)bq4[j].x | ((uint32_t)bq4[j].y << 16)) | 0x64006400u;
            uint32_t u23 = ((uint32_t)bq4[j].z | ((uint32_t)bq4[j].w << 16)) | 0x64006400u;
            __half2 q01 = __hsub2(u2h(u01), h1024);
            __half2 q23 = __hsub2(u2h(u23), h1024);
            uint32_t w01 = h2u(__hfma2(q01, u2h(s01), u2h(z01)));
            uint32_t w23 = h2u(__hfma2(q23, u2h(s23), u2h(z23)));
            asm volatile("st.shared.v2.b32 [%0], {%1,%2};"
                         :: "r"(base + (uint32_t)j * 1024u), "r"(w01), "r"(w23) : "memory");
        }
    };

    auto compute_half = [&](int st, int h) {   // ks = 2h, 2h+1
        uint32_t abase = sb + SM_A + (uint32_t)st * 32768u;
        uint32_t bbase = sb + SM_B + (uint32_t)st * 8192u + b_row;
#pragma unroll
        for (int ks = 2 * h; ks < 2 * h + 2; ks++) {
            uint32_t a[4][4];
#pragma unroll
            for (int mb = 0; mb < 4; mb++)
                ldsm_x4(a[mb], abase + a_row[mb] + ((((uint32_t)(2 * ks) + lq) ^ sx) << 4));
            uint32_t b[8][2];
#pragma unroll
            for (int p = 0; p < 4; p++)
                ldsm_x4_t(b[2 * p][0], b[2 * p][1], b[2 * p + 1][0], b[2 * p + 1][1],
                          bbase + (uint32_t)ks * 2048u + ((((uint32_t)(2 * p) + lq) ^ sx) << 4));
#pragma unroll
            for (int mb = 0; mb < 4; mb++)
#pragma unroll
                for (int nb = 0; nb < 8; nb++)
                    mma16816(d[mb][nb], a[mb], b[nb][0], b[nb][1]);
        }
    };

    // ---- prologue: chunk c0 into stage 0 ----
    prefetch_a(c0, 0);
    load_scales(c0);
    ldg_b(c0, 0); store_b(0, 0);
    ldg_b(c0, 1); store_b(0, 1);
    asm volatile("cp.async.wait_group 0;" ::: "memory");
    __syncthreads();

    // ---- main loop (double buffered, R4 structure) ----
    for (int i = 0; i < NITER_L; i++) {
        int c = c0 + i;
        int st = i & 1;
        if (i + 1 < NITER_L) {
            prefetch_a(c + 1, st ^ 1);
            load_scales(c + 1);
            ldg_b(c + 1, 0);
        }
        compute_half(st, 0);
        if (i + 1 < NITER_L) {
            store_b(st ^ 1, 0);
            ldg_b(c + 1, 1);
        }
        compute_half(st, 1);
        if (i + 1 < NITER_L) {
            store_b(st ^ 1, 1);
            asm volatile("cp.async.wait_group 0;" ::: "memory");
        }
        __syncthreads();
    }

    // ---- epilogue: merge partial sums via red.add ----
    const int gr = lane >> 2;
    const int c2 = (lane & 3) * 2;
#pragma unroll
    for (int mb = 0; mb < 4; mb++) {
        int m = w * 64 + mb * 16 + gr;
#pragma unroll
        for (int nb = 0; nb < 8; nb++) {
            int n = n0 + nb * 8 + c2;
            float* p0 = out + (size_t)m * NF + n;
            float* p1 = out + (size_t)(m + 8) * NF + n;
            atomicAdd(p0,     d[mb][nb][0]);
            atomicAdd(p0 + 1, d[mb][nb][1]);
            atomicAdd(p1,     d[mb][nb][2]);
            atomicAdd(p1 + 1, d[mb][nb][3]);
        }
    }
}

// ---------------------------------------------------------------------------
// kernel_launch
// ---------------------------------------------------------------------------
extern "C" void kernel_launch(void* const* d_in, const int* in_sizes, int n_in,
                              void* d_out, int out_size) {
    const float* x    = (const float*)d_in[0];
    const int*   qk   = (const int*)d_in[1];
    const float* qs   = (const float*)d_in[2];
    const float* qzb  = (const float*)d_in[3];
    const float* bias = (const float*)d_in[4];
    float* out = (float*)d_out;

    cudaFuncSetAttribute(gemm_kernel, cudaFuncAttributeMaxDynamicSharedMemorySize, SM_TOTAL);

    prep_x_kernel<<<(MROWS * KF / 2) / 256, 256>>>(x);
    init_out_kernel<<<(MROWS * NF / 4) / 256, 256>>>(bias, out);
    gemm_kernel<<<GRID, 128, SM_TOTAL>>>(qk, qs, qzb, out);
}

// round 9
// speedup vs baseline: 1.0014x; 1.0014x over previous
#include <cuda_runtime.h>
#include <cuda_fp16.h>
#include <cstdint>
#include <cstddef>

// ---------------------------------------------------------------------------
// Geometry
// ---------------------------------------------------------------------------
static constexpr int KF = 4096;
static constexpr int NF = 14336;
static constexpr int MROWS = 256;
static constexpr int NTILE = 64;               // per-CTA n extent
static constexpr int KQ = 4;                   // k quarters
static constexpr int GRID = (NF / NTILE) * KQ; // 896
static constexpr int KC = 64;                  // k per stage
static constexpr int NITER_L = KF / KC / KQ;   // 16 chunks per CTA

// fp16 image of x, pre-swizzled as A smem tile images:
// 64 tiles (one per 64-k chunk), each 256 rows x 128B = 32KB.
__device__ __align__(128) unsigned char g_xs[64 * 32768];

// Split-K partial sums: one fp32 [256 x 14336] tile per k-quarter (58.7 MB).
__device__ float g_part[KQ][(size_t)MROWS * NF];

// SMEM: A 2 x 32768 | B 2 x 8192  (per CTA)
static constexpr uint32_t SM_A = 0;
static constexpr uint32_t SM_B = 65536;
static constexpr uint32_t SM_TOTAL = 81920;

// ---------------------------------------------------------------------------
// Helpers
// ---------------------------------------------------------------------------
__device__ __forceinline__ __half2 u2h(uint32_t u) { return *reinterpret_cast<__half2*>(&u); }
__device__ __forceinline__ uint32_t h2u(__half2 h) { return *reinterpret_cast<uint32_t*>(&h); }

__device__ __forceinline__ void ldsm_x4(uint32_t (&r)[4], uint32_t addr) {
    asm volatile("ldmatrix.sync.aligned.m8n8.x4.shared.b16 {%0,%1,%2,%3}, [%4];"
                 : "=r"(r[0]), "=r"(r[1]), "=r"(r[2]), "=r"(r[3]) : "r"(addr));
}
__device__ __forceinline__ void ldsm_x4_t(uint32_t& r0, uint32_t& r1, uint32_t& r2, uint32_t& r3,
                                          uint32_t addr) {
    asm volatile("ldmatrix.sync.aligned.m8n8.x4.trans.shared.b16 {%0,%1,%2,%3}, [%4];"
                 : "=r"(r0), "=r"(r1), "=r"(r2), "=r"(r3) : "r"(addr));
}
__device__ __forceinline__ void mma16816(float (&d)[4], const uint32_t (&a)[4],
                                         uint32_t b0, uint32_t b1) {
    asm volatile("mma.sync.aligned.m16n8k16.row.col.f32.f16.f16.f32 "
                 "{%0,%1,%2,%3}, {%4,%5,%6,%7}, {%8,%9}, {%0,%1,%2,%3};"
                 : "+f"(d[0]), "+f"(d[1]), "+f"(d[2]), "+f"(d[3])
                 : "r"(a[0]), "r"(a[1]), "r"(a[2]), "r"(a[3]), "r"(b0), "r"(b1));
}

// ---------------------------------------------------------------------------
// Kernel 1: x fp32 -> fp16 pre-swizzled A tile images. 8 k-values per thread
// (one 16B swizzled store), 4x MLP on the loads.
// byte(m, kl) = m*128 + (((kl>>3)^(m&7))<<4) + (kl&7)*2
// ---------------------------------------------------------------------------
__global__ __launch_bounds__(256) void prep_x_kernel(const float* __restrict__ x) {
    int idx = blockIdx.x * 256 + threadIdx.x;      // 131072 threads
    int m   = idx >> 9;                             // 512 threads per m-row
    int kl8 = (idx & 511) * 8;                      // k base (8-aligned)
    const float* xp = x + (size_t)m * KF + kl8;
    float4 v0 = *reinterpret_cast<const float4*>(xp);
    float4 v1 = *reinterpret_cast<const float4*>(xp + 4);
    uint4 o;
    o.x = h2u(__floats2half2_rn(v0.x, v0.y));
    o.y = h2u(__floats2half2_rn(v0.z, v0.w));
    o.z = h2u(__floats2half2_rn(v1.x, v1.y));
    o.w = h2u(__floats2half2_rn(v1.z, v1.w));
    int c = kl8 >> 6, kl = kl8 & 63;
    uint32_t off = (uint32_t)m * 128u + ((((uint32_t)(kl >> 3)) ^ (uint32_t)(m & 7)) << 4);
    *reinterpret_cast<uint4*>(g_xs + (size_t)c * 32768 + off) = o;
}

// ---------------------------------------------------------------------------
// Kernel 2: GEMM. 896 CTAs x 128 threads (4 warps), 2 CTAs/SM.
// CTA: M=256, N=64, K=1024 (quarter). Warps 4(m) x 1(n); warp tile 64x64.
// Partials written (plain stores) to g_part[quarter].
// ---------------------------------------------------------------------------
__global__ __launch_bounds__(128, 2)
void gemm_kernel(const int* __restrict__ qk, const float* __restrict__ qs,
                 const float* __restrict__ qzb) {
    extern __shared__ unsigned char smem[];
    const uint32_t sb = (uint32_t)__cvta_generic_to_shared(smem);
    const int t = threadIdx.x, lane = t & 31, w = t >> 5;
    const int n0 = (blockIdx.x >> 2) * NTILE;
    const int kq = blockIdx.x & 3;
    const int c0 = kq * NITER_L;                   // first k-chunk of this quarter

    // ---- dequant mapping: nq = n quad (0..15), kw = k row base (0..7) ----
    const int nq = t & 15;
    const int kw = t >> 4;
    const uint32_t sts_base = (uint32_t)kw * 128u
                            + ((uint32_t)((nq >> 1) ^ kw) << 4) + (uint32_t)(nq & 1) * 8u;
    const int*   qbase = qk  + n0 + nq * 4;
    const float* sbase = qs  + n0 + nq * 4;
    const float* zbase = qzb + n0 + nq * 4;

    // ---- ldmatrix addressing ----
    const int l15 = lane & 15;
    const uint32_t sx = (uint32_t)(lane & 7);
    const uint32_t lq = (uint32_t)(lane >> 4);
    uint32_t a_row[4];
#pragma unroll
    for (int mb = 0; mb < 4; mb++)
        a_row[mb] = (uint32_t)(w * 64 + mb * 16 + l15) * 128u;
    const uint32_t b_row = (uint32_t)l15 * 128u;

    float d[4][8][4];
#pragma unroll
    for (int mb = 0; mb < 4; mb++)
#pragma unroll
        for (int nb = 0; nb < 8; nb++)
#pragma unroll
            for (int i = 0; i < 4; i++) d[mb][nb][i] = 0.0f;

    int4 bq4[4];
    uint32_t s01, s23, z01, z23;

    // ---- A prefetch: 32KB identity cp.async of pre-swizzled image ----
    auto prefetch_a = [&](int c, int st) {
        const unsigned char* asrc = g_xs + (size_t)c * 32768 + (size_t)t * 16;
        uint32_t adst = sb + SM_A + (uint32_t)st * 32768u + (uint32_t)t * 16u;
#pragma unroll
        for (int i = 0; i < 16; i++) {
            asm volatile("cp.async.cg.shared.global [%0], [%1], 16;"
                         :: "r"(adst + (uint32_t)i * 2048u), "l"(asrc + (size_t)i * 2048)
                         : "memory");
        }
        asm volatile("cp.async.commit_group;" ::: "memory");
    };

    auto load_scales = [&](int c) {
        int g = c >> 1;
        float4 s4 = *reinterpret_cast<const float4*>(sbase + (size_t)g * NF);
        float4 z4 = *reinterpret_cast<const float4*>(zbase + (size_t)g * NF);
        s01 = h2u(__floats2half2_rn(s4.x, s4.y)); s23 = h2u(__floats2half2_rn(s4.z, s4.w));
        z01 = h2u(__floats2half2_rn(z4.x, z4.y)); z23 = h2u(__floats2half2_rn(z4.z, z4.w));
    };

    auto ldg_b = [&](int c, int h) {           // rows k = kw + 8*(4h + j)
        const int* qp = qbase + (size_t)c * KC * NF + (size_t)(32 * h) * NF;
#pragma unroll
        for (int j = 0; j < 4; j++)
            bq4[j] = *reinterpret_cast<const int4*>(qp + (size_t)(kw + 8 * j) * NF);
    };

    auto store_b = [&](int st, int h) {
        const __half2 h1024 = u2h(0x64006400u);
        uint32_t base = sb + SM_B + (uint32_t)st * 8192u + sts_base + (uint32_t)h * 4096u;
#pragma unroll
        for (int j = 0; j < 4; j++) {
            uint32_t u01 = ((uint32_t)bq4[j].x | ((uint32_t)bq4[j].y << 16)) | 0x64006400u;
            uint32_t u23 = ((uint32_t)bq4[j].z | ((uint32_t)bq4[j].w << 16)) | 0x64006400u;
            __half2 q01 = __hsub2(u2h(u01), h1024);
            __half2 q23 = __hsub2(u2h(u23), h1024);
            uint32_t w01 = h2u(__hfma2(q01, u2h(s01), u2h(z01)));
            uint32_t w23 = h2u(__hfma2(q23, u2h(s23), u2h(z23)));
            asm volatile("st.shared.v2.b32 [%0], {%1,%2};"
                         :: "r"(base + (uint32_t)j * 1024u), "r"(w01), "r"(w23) : "memory");
        }
    };

    auto compute_half = [&](int st, int h) {   // ks = 2h, 2h+1
        uint32_t abase = sb + SM_A + (uint32_t)st * 32768u;
        uint32_t bbase = sb + SM_B + (uint32_t)st * 8192u + b_row;
#pragma unroll
        for (int ks = 2 * h; ks < 2 * h + 2; ks++) {
            uint32_t a[4][4];
#pragma unroll
            for (int mb = 0; mb < 4; mb++)
                ldsm_x4(a[mb], abase + a_row[mb] + ((((uint32_t)(2 * ks) + lq) ^ sx) << 4));
            uint32_t b[8][2];
#pragma unroll
            for (int p = 0; p < 4; p++)
                ldsm_x4_t(b[2 * p][0], b[2 * p][1], b[2 * p + 1][0], b[2 * p + 1][1],
                          bbase + (uint32_t)ks * 2048u + ((((uint32_t)(2 * p) + lq) ^ sx) << 4));
#pragma unroll
            for (int mb = 0; mb < 4; mb++)
#pragma unroll
                for (int nb = 0; nb < 8; nb++)
                    mma16816(d[mb][nb], a[mb], b[nb][0], b[nb][1]);
        }
    };

    // ---- prologue: chunk c0 into stage 0 ----
    prefetch_a(c0, 0);
    load_scales(c0);
    ldg_b(c0, 0); store_b(0, 0);
    ldg_b(c0, 1); store_b(0, 1);
    asm volatile("cp.async.wait_group 0;" ::: "memory");
    __syncthreads();

    // ---- main loop (double buffered) ----
    for (int i = 0; i < NITER_L; i++) {
        int c = c0 + i;
        int st = i & 1;
        if (i + 1 < NITER_L) {
            prefetch_a(c + 1, st ^ 1);
            load_scales(c + 1);
            ldg_b(c + 1, 0);
        }
        compute_half(st, 0);
        if (i + 1 < NITER_L) {
            store_b(st ^ 1, 0);
            ldg_b(c + 1, 1);
        }
        compute_half(st, 1);
        if (i + 1 < NITER_L) {
            store_b(st ^ 1, 1);
            asm volatile("cp.async.wait_group 0;" ::: "memory");
        }
        __syncthreads();
    }

    // ---- epilogue: plain stores of the partial tile ----
    float* pout = g_part[kq];
    const int gr = lane >> 2;
    const int c2 = (lane & 3) * 2;
#pragma unroll
    for (int mb = 0; mb < 4; mb++) {
        int m = w * 64 + mb * 16 + gr;
#pragma unroll
        for (int nb = 0; nb < 8; nb++) {
            int n = n0 + nb * 8 + c2;
            float2 o0, o1;
            o0.x = d[mb][nb][0]; o0.y = d[mb][nb][1];
            o1.x = d[mb][nb][2]; o1.y = d[mb][nb][3];
            *reinterpret_cast<float2*>(pout + (size_t)m * NF + n)       = o0;
            *reinterpret_cast<float2*>(pout + (size_t)(m + 8) * NF + n) = o1;
        }
    }
}

// ---------------------------------------------------------------------------
// Kernel 3: out = p0 + p1 + p2 + p3 + bias   (float4 per thread)
// ---------------------------------------------------------------------------
__global__ __launch_bounds__(256) void reduce_kernel(const float* __restrict__ bias,
                                                     float* __restrict__ out) {
    size_t idx = (size_t)blockIdx.x * 256 + threadIdx.x;   // 917504 float4s
    size_t off = idx * 4;
    int n = (int)(off % NF);
    float4 p0 = *reinterpret_cast<const float4*>(&g_part[0][off]);
    float4 p1 = *reinterpret_cast<const float4*>(&g_part[1][off]);
    float4 p2 = *reinterpret_cast<const float4*>(&g_part[2][off]);
    float4 p3 = *reinterpret_cast<const float4*>(&g_part[3][off]);
    float4 b4 = *reinterpret_cast<const float4*>(bias + n);
    float4 o;
    o.x = p0.x + p1.x + p2.x + p3.x + b4.x;
    o.y = p0.y + p1.y + p2.y + p3.y + b4.y;
    o.z = p0.z + p1.z + p2.z + p3.z + b4.z;
    o.w = p0.w + p1.w + p2.w + p3.w + b4.w;
    *reinterpret_cast<float4*>(out + off) = o;
}

// ---------------------------------------------------------------------------
// kernel_launch
// ---------------------------------------------------------------------------
extern "C" void kernel_launch(void* const* d_in, const int* in_sizes, int n_in,
                              void* d_out, int out_size) {
    const float* x    = (const float*)d_in[0];
    const int*   qk   = (const int*)d_in[1];
    const float* qs   = (const float*)d_in[2];
    const float* qzb  = (const float*)d_in[3];
    const float* bias = (const float*)d_in[4];
    float* out = (float*)d_out;

    cudaFuncSetAttribute(gemm_kernel, cudaFuncAttributeMaxDynamicSharedMemorySize, SM_TOTAL);

    prep_x_kernel<<<512, 256>>>(x);
    gemm_kernel<<<GRID, 128, SM_TOTAL>>>(qk, qs, qzb);
    reduce_kernel<<<(MROWS * NF / 4) / 256, 256>>>(bias, out);
}